// round 16
// baseline (speedup 1.0000x reference)
#include <cuda_runtime.h>
#include <cuda_bf16.h>
#include <mma.h>
#include <math.h>

using namespace nvcuda;

#define NN 50000
#define EE 800000
#define ET (EE + NN)
#define HC 64
#define F_IN 128
#define OUTD 16

__device__ __align__(16) float g_xl[(size_t)NN * HC];
__device__ __align__(16) float g_xr[(size_t)NN * HC];
__device__ __align__(16) float g_h [(size_t)NN * HC];
__device__ __align__(16) float g_agg[(size_t)NN * HC];
__device__ int g_csrsrc[(size_t)ET];
__device__ int g_rank[(size_t)ET];
__device__ int g_start[NN];
__device__ int g_cnt[NN];
__device__ int g_cursor;
__device__ int g_is64;

// ---------------------------------------------------------------------------
// reset + dtype detect
__global__ void k_reset(const int* __restrict__ ei) {
    int n = blockIdx.x * blockDim.x + threadIdx.x;
    if (n < NN) g_cnt[n] = 0;
    if (n == 0) {
        g_cursor = 0;
        int is64 = 1;
        for (int i = 0; i < 256; i++)
            if (ei[2 * i + 1] != 0) { is64 = 0; break; }
        g_is64 = is64;
    }
}

__device__ __forceinline__ int edge_dst(const int* ei, int e) {
    if (e >= EE) return e - EE;
    return g_is64 ? (int)((const long long*)ei)[(size_t)EE + e] : ei[EE + e];
}
__device__ __forceinline__ int edge_src(const int* ei, int e) {
    if (e >= EE) return e - EE;
    return g_is64 ? (int)((const long long*)ei)[e] : ei[e];
}

// count + record rank (the atomic return value we used to discard)
__global__ void k_count(const int* __restrict__ ei) {
    int e = blockIdx.x * blockDim.x + threadIdx.x;
    if (e >= ET) return;
    g_rank[e] = atomicAdd(&g_cnt[edge_dst(ei, e)], 1);
}

// warp-aggregated ticket allocation of CSR row starts
__global__ void k_alloc() {
    int n = blockIdx.x * blockDim.x + threadIdx.x;
    int lane = threadIdx.x & 31;
    int c = (n < NN) ? g_cnt[n] : 0;
    int s = c;
    #pragma unroll
    for (int o = 1; o < 32; o <<= 1) {
        int v = __shfl_up_sync(0xffffffffu, s, o);
        if (lane >= o) s += v;
    }
    int total = __shfl_sync(0xffffffffu, s, 31);
    int base = 0;
    if (lane == 31) base = atomicAdd(&g_cursor, total);
    base = __shfl_sync(0xffffffffu, base, 31);
    if (n < NN) g_start[n] = base + s - c;
}

// atomic-free scatter: position = start[dst] + rank[e]
__global__ void k_scatter(const int* __restrict__ ei) {
    int e = blockIdx.x * blockDim.x + threadIdx.x;
    if (e >= ET) return;
    int s = edge_src(ei, e);
    int d = edge_dst(ei, e);
    g_csrsrc[g_start[d] + g_rank[e]] = s;
}

// ---------------------------------------------------------------------------
// 3xTF32 tensor-core dual GEMM: outL = X @ Wl + bl, outR = X @ Wr + br.
// BM=64, both 64-col outputs per block. 8 warps: warp = (mtile 0..3, half L/R),
// each computing a 16x64 strip via 4 m16n16k8 acc fragments.
// Precision: v = hi + lo (tf32 split); acc += hi*hi + hi*lo + lo*hi.
template <int KT>
__global__ void __launch_bounds__(256, 2)
k_gemm_tc(const float* __restrict__ X,
          const float* __restrict__ Wl, const float* __restrict__ bl,
          const float* __restrict__ Wr, const float* __restrict__ br,
          float* __restrict__ outL, float* __restrict__ outR) {
    __shared__ float Ahi[64][20], Alo[64][20];          // [m][k]
    __shared__ float Bhi[2][16][68], Blo[2][16][68];    // [half][k][n]
    __shared__ float stage[8][16][20];

    const int tid  = threadIdx.x;
    const int warp = tid >> 5;
    const int lane = tid & 31;
    const int mt   = warp & 3;
    const int half = warp >> 2;
    const int m0   = blockIdx.x * 64;

    wmma::fragment<wmma::accumulator, 16, 16, 8, float> acc[4];
    #pragma unroll
    for (int nt = 0; nt < 4; nt++) wmma::fill_fragment(acc[nt], 0.f);

    for (int kc = 0; kc < KT; kc += 16) {
        // A tile 64x16: one float4 per thread, split into tf32 hi/lo
        {
            int r = tid >> 2, c4 = tid & 3;
            int m = m0 + r;
            float4 v = make_float4(0.f, 0.f, 0.f, 0.f);
            if (m < NN) v = *(const float4*)(X + (size_t)m * KT + kc + c4 * 4);
            float h0 = wmma::__float_to_tf32(v.x);
            float h1 = wmma::__float_to_tf32(v.y);
            float h2 = wmma::__float_to_tf32(v.z);
            float h3 = wmma::__float_to_tf32(v.w);
            int c = c4 * 4;
            Ahi[r][c + 0] = h0; Alo[r][c + 0] = wmma::__float_to_tf32(v.x - h0);
            Ahi[r][c + 1] = h1; Alo[r][c + 1] = wmma::__float_to_tf32(v.y - h1);
            Ahi[r][c + 2] = h2; Alo[r][c + 2] = wmma::__float_to_tf32(v.z - h2);
            Ahi[r][c + 3] = h3; Alo[r][c + 3] = wmma::__float_to_tf32(v.w - h3);
        }
        // B tiles (L and R) 16x64 each: one float4 per thread per matrix
        {
            int k = tid >> 4, n4 = tid & 15;
            int c = n4 * 4;
            float4 w = *(const float4*)(Wl + (size_t)(kc + k) * 64 + c);
            float h0 = wmma::__float_to_tf32(w.x);
            float h1 = wmma::__float_to_tf32(w.y);
            float h2 = wmma::__float_to_tf32(w.z);
            float h3 = wmma::__float_to_tf32(w.w);
            Bhi[0][k][c + 0] = h0; Blo[0][k][c + 0] = wmma::__float_to_tf32(w.x - h0);
            Bhi[0][k][c + 1] = h1; Blo[0][k][c + 1] = wmma::__float_to_tf32(w.y - h1);
            Bhi[0][k][c + 2] = h2; Blo[0][k][c + 2] = wmma::__float_to_tf32(w.z - h2);
            Bhi[0][k][c + 3] = h3; Blo[0][k][c + 3] = wmma::__float_to_tf32(w.w - h3);
            w = *(const float4*)(Wr + (size_t)(kc + k) * 64 + c);
            h0 = wmma::__float_to_tf32(w.x);
            h1 = wmma::__float_to_tf32(w.y);
            h2 = wmma::__float_to_tf32(w.z);
            h3 = wmma::__float_to_tf32(w.w);
            Bhi[1][k][c + 0] = h0; Blo[1][k][c + 0] = wmma::__float_to_tf32(w.x - h0);
            Bhi[1][k][c + 1] = h1; Blo[1][k][c + 1] = wmma::__float_to_tf32(w.y - h1);
            Bhi[1][k][c + 2] = h2; Blo[1][k][c + 2] = wmma::__float_to_tf32(w.z - h2);
            Bhi[1][k][c + 3] = h3; Blo[1][k][c + 3] = wmma::__float_to_tf32(w.w - h3);
        }
        __syncthreads();

        #pragma unroll
        for (int ks = 0; ks < 2; ks++) {
            wmma::fragment<wmma::matrix_a, 16, 16, 8, wmma::precision::tf32, wmma::row_major> ahi, alo;
            wmma::load_matrix_sync(ahi, &Ahi[mt * 16][ks * 8], 20);
            wmma::load_matrix_sync(alo, &Alo[mt * 16][ks * 8], 20);
            #pragma unroll
            for (int nt = 0; nt < 4; nt++) {
                wmma::fragment<wmma::matrix_b, 16, 16, 8, wmma::precision::tf32, wmma::row_major> bhi, blo;
                wmma::load_matrix_sync(bhi, &Bhi[half][ks * 8][nt * 16], 68);
                wmma::load_matrix_sync(blo, &Blo[half][ks * 8][nt * 16], 68);
                wmma::mma_sync(acc[nt], ahi, bhi, acc[nt]);
                wmma::mma_sync(acc[nt], ahi, blo, acc[nt]);
                wmma::mma_sync(acc[nt], alo, bhi, acc[nt]);
            }
        }
        __syncthreads();
    }

    // Epilogue: stage through smem, add bias, tail-guarded stores.
    const float* bias = half ? br : bl;
    float* out        = half ? outR : outL;
    const int rr = lane >> 1;
    const int cc = (lane & 1) * 8;
    const int m  = m0 + mt * 16 + rr;
    #pragma unroll
    for (int nt = 0; nt < 4; nt++) {
        wmma::store_matrix_sync(&stage[warp][0][0], acc[nt], 20, wmma::mem_row_major);
        __syncwarp();
        if (m < NN) {
            int n0 = nt * 16 + cc;
            float4 v0 = *(const float4*)&stage[warp][rr][cc];
            float4 v1 = *(const float4*)&stage[warp][rr][cc + 4];
            v0.x += bias[n0 + 0]; v0.y += bias[n0 + 1];
            v0.z += bias[n0 + 2]; v0.w += bias[n0 + 3];
            v1.x += bias[n0 + 4]; v1.y += bias[n0 + 5];
            v1.z += bias[n0 + 6]; v1.w += bias[n0 + 7];
            *(float4*)(out + (size_t)m * 64 + n0)     = v0;
            *(float4*)(out + (size_t)m * 64 + n0 + 4) = v1;
        }
        __syncwarp();
    }
}

// ---------------------------------------------------------------------------
// CSR edge pass: one WARP per destination node; two 16-lane slots, x2 unroll.
// LAYER 0: h = relu(v + b1) -> g_h. LAYER 1: v -> g_agg.
template <int LAYER>
__global__ void k_edge_csr(const float* __restrict__ att,
                           const float* __restrict__ bias) {
    int t = blockIdx.x * blockDim.x + threadIdx.x;
    int n = t >> 5;
    if (n >= NN) return;
    const int lane = threadIdx.x & 31;
    const int sub = lane >> 4;
    const int g = lane & 15;
    const unsigned mask8 = 0xffu << (lane & 24);

    const int beg = g_start[n];
    const int cnt = g_cnt[n];

    float4 xr4 = *(const float4*)(g_xr + (size_t)n * 64 + g * 4);
    int head = (lane >> 3) & 1;
    float4 a4 = *(const float4*)(att + head * 32 + (g & 7) * 4);

    float acc0 = 0.f, acc1 = 0.f, acc2 = 0.f, acc3 = 0.f, dn = 0.f;

    int i = 0;
    for (; i + 4 <= cnt; i += 4) {
        int sA = __ldg(&g_csrsrc[beg + i + sub]);
        int sB = __ldg(&g_csrsrc[beg + i + 2 + sub]);
        float4 xA = __ldg((const float4*)(g_xl + (size_t)sA * 64 + g * 4));
        float4 xB = __ldg((const float4*)(g_xl + (size_t)sB * 64 + g * 4));

        float pA, pB;
        {
            float u0 = xA.x + xr4.x, u1 = xA.y + xr4.y, u2 = xA.z + xr4.z, u3 = xA.w + xr4.w;
            u0 = u0 > 0.f ? u0 : 0.2f * u0;  u1 = u1 > 0.f ? u1 : 0.2f * u1;
            u2 = u2 > 0.f ? u2 : 0.2f * u2;  u3 = u3 > 0.f ? u3 : 0.2f * u3;
            pA = u0 * a4.x + u1 * a4.y + u2 * a4.z + u3 * a4.w;
        }
        {
            float u0 = xB.x + xr4.x, u1 = xB.y + xr4.y, u2 = xB.z + xr4.z, u3 = xB.w + xr4.w;
            u0 = u0 > 0.f ? u0 : 0.2f * u0;  u1 = u1 > 0.f ? u1 : 0.2f * u1;
            u2 = u2 > 0.f ? u2 : 0.2f * u2;  u3 = u3 > 0.f ? u3 : 0.2f * u3;
            pB = u0 * a4.x + u1 * a4.y + u2 * a4.z + u3 * a4.w;
        }
        pA += __shfl_xor_sync(mask8, pA, 1);
        pB += __shfl_xor_sync(mask8, pB, 1);
        pA += __shfl_xor_sync(mask8, pA, 2);
        pB += __shfl_xor_sync(mask8, pB, 2);
        pA += __shfl_xor_sync(mask8, pA, 4);
        pB += __shfl_xor_sync(mask8, pB, 4);
        float eA = __expf(pA);
        float eB = __expf(pB);
        dn += eA + eB;
        acc0 += eA * xA.x + eB * xB.x;
        acc1 += eA * xA.y + eB * xB.y;
        acc2 += eA * xA.z + eB * xB.z;
        acc3 += eA * xA.w + eB * xB.w;
    }
    if (i + 2 <= cnt) {
        int sA = __ldg(&g_csrsrc[beg + i + sub]);
        float4 xA = __ldg((const float4*)(g_xl + (size_t)sA * 64 + g * 4));
        float u0 = xA.x + xr4.x, u1 = xA.y + xr4.y, u2 = xA.z + xr4.z, u3 = xA.w + xr4.w;
        u0 = u0 > 0.f ? u0 : 0.2f * u0;  u1 = u1 > 0.f ? u1 : 0.2f * u1;
        u2 = u2 > 0.f ? u2 : 0.2f * u2;  u3 = u3 > 0.f ? u3 : 0.2f * u3;
        float pA = u0 * a4.x + u1 * a4.y + u2 * a4.z + u3 * a4.w;
        pA += __shfl_xor_sync(mask8, pA, 1);
        pA += __shfl_xor_sync(mask8, pA, 2);
        pA += __shfl_xor_sync(mask8, pA, 4);
        float eA = __expf(pA);
        dn += eA;
        acc0 += eA * xA.x; acc1 += eA * xA.y;
        acc2 += eA * xA.z; acc3 += eA * xA.w;
        i += 2;
    }
    if (i < cnt && sub == 0) {
        int sA = __ldg(&g_csrsrc[beg + i]);
        float4 xA = __ldg((const float4*)(g_xl + (size_t)sA * 64 + g * 4));
        float u0 = xA.x + xr4.x, u1 = xA.y + xr4.y, u2 = xA.z + xr4.z, u3 = xA.w + xr4.w;
        u0 = u0 > 0.f ? u0 : 0.2f * u0;  u1 = u1 > 0.f ? u1 : 0.2f * u1;
        u2 = u2 > 0.f ? u2 : 0.2f * u2;  u3 = u3 > 0.f ? u3 : 0.2f * u3;
        float pA = u0 * a4.x + u1 * a4.y + u2 * a4.z + u3 * a4.w;
        pA += __shfl_xor_sync(mask8, pA, 1);
        pA += __shfl_xor_sync(mask8, pA, 2);
        pA += __shfl_xor_sync(mask8, pA, 4);
        float eA = __expf(pA);
        dn += eA;
        acc0 += eA * xA.x; acc1 += eA * xA.y;
        acc2 += eA * xA.z; acc3 += eA * xA.w;
    }

    acc0 += __shfl_xor_sync(0xffffffffu, acc0, 16);
    acc1 += __shfl_xor_sync(0xffffffffu, acc1, 16);
    acc2 += __shfl_xor_sync(0xffffffffu, acc2, 16);
    acc3 += __shfl_xor_sync(0xffffffffu, acc3, 16);
    dn   += __shfl_xor_sync(0xffffffffu, dn, 16);

    if (sub == 0) {
        float r = 1.f / dn;
        int c = g * 4;
        float4 v;
        v.x = acc0 * r; v.y = acc1 * r; v.z = acc2 * r; v.w = acc3 * r;
        if (LAYER == 0) {
            v.x += bias[c + 0]; v.y += bias[c + 1];
            v.z += bias[c + 2]; v.w += bias[c + 3];
            v.x = v.x > 0.f ? v.x : 0.f;
            v.y = v.y > 0.f ? v.y : 0.f;
            v.z = v.z > 0.f ? v.z : 0.f;
            v.w = v.w > 0.f ? v.w : 0.f;
            *(float4*)(g_h + (size_t)n * 64 + c) = v;
        } else {
            *(float4*)(g_agg + (size_t)n * 64 + c) = v;
        }
    }
}

// ---------------------------------------------------------------------------
// Final head: b2 + BN + relu -> emb (Wp,bp) -> risk. Thread per node.
__global__ void k_final(const float* __restrict__ b2,
                        const float* __restrict__ bn_g, const float* __restrict__ bn_b,
                        const float* __restrict__ bn_m, const float* __restrict__ bn_v,
                        const float* __restrict__ Wp, const float* __restrict__ bp,
                        const float* __restrict__ Wh1, const float* __restrict__ bh1,
                        const float* __restrict__ Wh2, const float* __restrict__ bh2,
                        float* __restrict__ out) {
    int n = blockIdx.x * blockDim.x + threadIdx.x;
    if (n >= NN) return;

    float h[64];
    #pragma unroll
    for (int i = 0; i < 64; i++) {
        float v = g_agg[(size_t)n * 64 + i] + b2[i];
        v = (v - bn_m[i]) * rsqrtf(bn_v[i] + 1e-5f) * bn_g[i] + bn_b[i];
        h[i] = v > 0.f ? v : 0.f;
    }
    float emb[16];
    #pragma unroll
    for (int j = 0; j < 16; j++) emb[j] = bp[j];
    #pragma unroll
    for (int k = 0; k < 64; k++) {
        float hk = h[k];
        #pragma unroll
        for (int j = 0; j < 16; j++) emb[j] += hk * Wp[k * 16 + j];
    }
    #pragma unroll
    for (int j = 0; j < 16; j++) out[(size_t)n * 16 + j] = emb[j];

    float hid[8];
    #pragma unroll
    for (int j = 0; j < 8; j++) {
        float s = bh1[j];
        #pragma unroll
        for (int k = 0; k < 16; k++) s += emb[k] * Wh1[k * 8 + j];
        hid[j] = s > 0.f ? s : 0.f;
    }
    float risk = bh2[0];
    #pragma unroll
    for (int j = 0; j < 8; j++) risk += hid[j] * Wh2[j];
    out[(size_t)NN * 16 + n] = risk;
}

// ---------------------------------------------------------------------------
extern "C" void kernel_launch(void* const* d_in, const int* in_sizes, int n_in,
                              void* d_out, int out_size) {
    const float* x    = (const float*)d_in[0];
    const int*   ei   = (const int*)d_in[1];
    const float* Wl1  = (const float*)d_in[2];
    const float* bl1  = (const float*)d_in[3];
    const float* Wr1  = (const float*)d_in[4];
    const float* br1  = (const float*)d_in[5];
    const float* att1 = (const float*)d_in[6];
    const float* b1   = (const float*)d_in[7];
    const float* Wl2  = (const float*)d_in[8];
    const float* bl2  = (const float*)d_in[9];
    const float* Wr2  = (const float*)d_in[10];
    const float* br2  = (const float*)d_in[11];
    const float* att2 = (const float*)d_in[12];
    const float* b2   = (const float*)d_in[13];
    const float* bn_g = (const float*)d_in[14];
    const float* bn_b = (const float*)d_in[15];
    const float* bn_m = (const float*)d_in[16];
    const float* bn_v = (const float*)d_in[17];
    const float* Wp   = (const float*)d_in[18];
    const float* bp   = (const float*)d_in[19];
    const float* Wh1  = (const float*)d_in[20];
    const float* bh1  = (const float*)d_in[21];
    const float* Wh2  = (const float*)d_in[22];
    const float* bh2  = (const float*)d_in[23];
    float* out = (float*)d_out;

    float *p_xl, *p_xr, *p_h;
    cudaGetSymbolAddress((void**)&p_xl, g_xl);
    cudaGetSymbolAddress((void**)&p_xr, g_xr);
    cudaGetSymbolAddress((void**)&p_h,  g_h);

    const int RB = (NN + 255) / 256;
    const int CB = (ET + 255) / 256;
    const int GB = (NN + 63) / 64;
    const int WB = (NN * 32 + 255) / 256;

    k_reset<<<RB, 256>>>(ei);
    k_count<<<CB, 256>>>(ei);
    k_alloc<<<RB, 256>>>();
    k_scatter<<<CB, 256>>>(ei);
    k_gemm_tc<F_IN><<<GB, 256>>>(x, Wl1, bl1, Wr1, br1, p_xl, p_xr);
    k_edge_csr<0><<<WB, 256>>>(att1, b1);
    k_gemm_tc<HC><<<GB, 256>>>(p_h, Wl2, bl2, Wr2, br2, p_xl, p_xr);
    k_edge_csr<1><<<WB, 256>>>(att2, nullptr);
    k_final<<<(NN + 127) / 128, 128>>>(b2, bn_g, bn_b, bn_m, bn_v,
                                       Wp, bp, Wh1, bh1, Wh2, bh2, out);
}

// round 17
// speedup vs baseline: 1.3866x; 1.3866x over previous
#include <cuda_runtime.h>
#include <cuda_bf16.h>
#include <math.h>

#define NN 50000
#define EE 800000
#define ET (EE + NN)
#define HC 64
#define F_IN 128
#define OUTD 16

__device__ __align__(16) float g_xl[(size_t)NN * HC];
__device__ __align__(16) float g_xr[(size_t)NN * HC];
__device__ __align__(16) float g_h [(size_t)NN * HC];
__device__ __align__(16) float g_agg[(size_t)NN * HC];
__device__ int g_csrsrc[(size_t)ET];
__device__ int g_rank[(size_t)ET];
__device__ int g_start[NN];
__device__ int g_cnt[NN];
__device__ int g_cursor;
__device__ int g_is64;

// ---------------------------------------------------------------------------
// reset + dtype detect
__global__ void k_reset(const int* __restrict__ ei) {
    int n = blockIdx.x * blockDim.x + threadIdx.x;
    if (n < NN) g_cnt[n] = 0;
    if (n == 0) {
        g_cursor = 0;
        int is64 = 1;
        for (int i = 0; i < 256; i++)
            if (ei[2 * i + 1] != 0) { is64 = 0; break; }
        g_is64 = is64;
    }
}

__device__ __forceinline__ int edge_dst(const int* ei, int e) {
    if (e >= EE) return e - EE;
    return g_is64 ? (int)((const long long*)ei)[(size_t)EE + e] : ei[EE + e];
}
__device__ __forceinline__ int edge_src(const int* ei, int e) {
    if (e >= EE) return e - EE;
    return g_is64 ? (int)((const long long*)ei)[e] : ei[e];
}

// count + record rank (the atomic return value is the within-dst rank)
__global__ void k_count(const int* __restrict__ ei) {
    int e = blockIdx.x * blockDim.x + threadIdx.x;
    if (e >= ET) return;
    g_rank[e] = atomicAdd(&g_cnt[edge_dst(ei, e)], 1);
}

// warp-aggregated ticket allocation of CSR row starts
__global__ void k_alloc() {
    int n = blockIdx.x * blockDim.x + threadIdx.x;
    int lane = threadIdx.x & 31;
    int c = (n < NN) ? g_cnt[n] : 0;
    int s = c;
    #pragma unroll
    for (int o = 1; o < 32; o <<= 1) {
        int v = __shfl_up_sync(0xffffffffu, s, o);
        if (lane >= o) s += v;
    }
    int total = __shfl_sync(0xffffffffu, s, 31);
    int base = 0;
    if (lane == 31) base = atomicAdd(&g_cursor, total);
    base = __shfl_sync(0xffffffffu, base, 31);
    if (n < NN) g_start[n] = base + s - c;
}

// atomic-free scatter: position = start[dst] + rank[e]
__global__ void k_scatter(const int* __restrict__ ei) {
    int e = blockIdx.x * blockDim.x + threadIdx.x;
    if (e >= ET) return;
    int s = edge_src(ei, e);
    int d = edge_dst(ei, e);
    g_csrsrc[g_start[d] + g_rank[e]] = s;
}

// ---------------------------------------------------------------------------
// Fused dual SGEMM: outL = X @ Wl + bl, outR = X @ Wr + br (shared A tile).
// BM=64, BN=64, BK=16, 256 threads, TM=TN=4. (fp32 FFMA — at roofline)
template <int KT>
__global__ void __launch_bounds__(256, 3)
k_gemm_fused(const float* __restrict__ X,
             const float* __restrict__ Wl, const float* __restrict__ bl,
             const float* __restrict__ Wr, const float* __restrict__ br,
             float* __restrict__ outL, float* __restrict__ outR) {
    __shared__ float As[16][68];
    __shared__ float WsL[16][64];
    __shared__ float WsR[16][64];

    const int tid = threadIdx.x;
    const int m0 = blockIdx.x * 64;
    const int tx = tid & 15;
    const int ty = tid >> 4;

    float accL[4][4] = {};
    float accR[4][4] = {};

    for (int kc = 0; kc < KT; kc += 16) {
        {
            int r  = tid >> 2;
            int c4 = tid & 3;
            int m  = m0 + r;
            float4 v = make_float4(0.f, 0.f, 0.f, 0.f);
            if (m < NN) v = *(const float4*)(X + (size_t)m * KT + kc + c4 * 4);
            As[c4 * 4 + 0][r] = v.x;
            As[c4 * 4 + 1][r] = v.y;
            As[c4 * 4 + 2][r] = v.z;
            As[c4 * 4 + 3][r] = v.w;
        }
        {
            int k  = tid >> 4;
            int c4 = tid & 15;
            *(float4*)&WsL[k][c4 * 4] = *(const float4*)(Wl + (size_t)(kc + k) * 64 + c4 * 4);
            *(float4*)&WsR[k][c4 * 4] = *(const float4*)(Wr + (size_t)(kc + k) * 64 + c4 * 4);
        }
        __syncthreads();
        #pragma unroll
        for (int kk = 0; kk < 16; kk++) {
            float a[4], bL[4], bR[4];
            *(float4*)a  = *(const float4*)&As[kk][ty * 4];
            *(float4*)bL = *(const float4*)&WsL[kk][tx * 4];
            *(float4*)bR = *(const float4*)&WsR[kk][tx * 4];
            #pragma unroll
            for (int i = 0; i < 4; i++)
                #pragma unroll
                for (int j = 0; j < 4; j++) {
                    accL[i][j] += a[i] * bL[j];
                    accR[i][j] += a[i] * bR[j];
                }
        }
        __syncthreads();
    }

    float4 bvL = *(const float4*)(bl + tx * 4);
    float4 bvR = *(const float4*)(br + tx * 4);
    #pragma unroll
    for (int i = 0; i < 4; i++) {
        int m = m0 + ty * 4 + i;
        if (m < NN) {
            float4 r;
            r.x = accL[i][0] + bvL.x; r.y = accL[i][1] + bvL.y;
            r.z = accL[i][2] + bvL.z; r.w = accL[i][3] + bvL.w;
            *(float4*)(outL + (size_t)m * 64 + tx * 4) = r;
            r.x = accR[i][0] + bvR.x; r.y = accR[i][1] + bvR.y;
            r.z = accR[i][2] + bvR.z; r.w = accR[i][3] + bvR.w;
            *(float4*)(outR + (size_t)m * 64 + tx * 4) = r;
        }
    }
}

// ---------------------------------------------------------------------------
// CSR edge pass: one WARP per destination node; two 16-lane slots, x2 unroll.
// LAYER 0: h = relu(v + b1) -> g_h. LAYER 1: v -> g_agg.
template <int LAYER>
__global__ void k_edge_csr(const float* __restrict__ att,
                           const float* __restrict__ bias) {
    int t = blockIdx.x * blockDim.x + threadIdx.x;
    int n = t >> 5;
    if (n >= NN) return;
    const int lane = threadIdx.x & 31;
    const int sub = lane >> 4;
    const int g = lane & 15;
    const unsigned mask8 = 0xffu << (lane & 24);

    const int beg = g_start[n];
    const int cnt = g_cnt[n];

    float4 xr4 = *(const float4*)(g_xr + (size_t)n * 64 + g * 4);
    int head = (lane >> 3) & 1;
    float4 a4 = *(const float4*)(att + head * 32 + (g & 7) * 4);

    float acc0 = 0.f, acc1 = 0.f, acc2 = 0.f, acc3 = 0.f, dn = 0.f;

    int i = 0;
    for (; i + 4 <= cnt; i += 4) {
        int sA = __ldg(&g_csrsrc[beg + i + sub]);
        int sB = __ldg(&g_csrsrc[beg + i + 2 + sub]);
        float4 xA = __ldg((const float4*)(g_xl + (size_t)sA * 64 + g * 4));
        float4 xB = __ldg((const float4*)(g_xl + (size_t)sB * 64 + g * 4));

        float pA, pB;
        {
            float u0 = xA.x + xr4.x, u1 = xA.y + xr4.y, u2 = xA.z + xr4.z, u3 = xA.w + xr4.w;
            u0 = u0 > 0.f ? u0 : 0.2f * u0;  u1 = u1 > 0.f ? u1 : 0.2f * u1;
            u2 = u2 > 0.f ? u2 : 0.2f * u2;  u3 = u3 > 0.f ? u3 : 0.2f * u3;
            pA = u0 * a4.x + u1 * a4.y + u2 * a4.z + u3 * a4.w;
        }
        {
            float u0 = xB.x + xr4.x, u1 = xB.y + xr4.y, u2 = xB.z + xr4.z, u3 = xB.w + xr4.w;
            u0 = u0 > 0.f ? u0 : 0.2f * u0;  u1 = u1 > 0.f ? u1 : 0.2f * u1;
            u2 = u2 > 0.f ? u2 : 0.2f * u2;  u3 = u3 > 0.f ? u3 : 0.2f * u3;
            pB = u0 * a4.x + u1 * a4.y + u2 * a4.z + u3 * a4.w;
        }
        pA += __shfl_xor_sync(mask8, pA, 1);
        pB += __shfl_xor_sync(mask8, pB, 1);
        pA += __shfl_xor_sync(mask8, pA, 2);
        pB += __shfl_xor_sync(mask8, pB, 2);
        pA += __shfl_xor_sync(mask8, pA, 4);
        pB += __shfl_xor_sync(mask8, pB, 4);
        float eA = __expf(pA);
        float eB = __expf(pB);
        dn += eA + eB;
        acc0 += eA * xA.x + eB * xB.x;
        acc1 += eA * xA.y + eB * xB.y;
        acc2 += eA * xA.z + eB * xB.z;
        acc3 += eA * xA.w + eB * xB.w;
    }
    if (i + 2 <= cnt) {
        int sA = __ldg(&g_csrsrc[beg + i + sub]);
        float4 xA = __ldg((const float4*)(g_xl + (size_t)sA * 64 + g * 4));
        float u0 = xA.x + xr4.x, u1 = xA.y + xr4.y, u2 = xA.z + xr4.z, u3 = xA.w + xr4.w;
        u0 = u0 > 0.f ? u0 : 0.2f * u0;  u1 = u1 > 0.f ? u1 : 0.2f * u1;
        u2 = u2 > 0.f ? u2 : 0.2f * u2;  u3 = u3 > 0.f ? u3 : 0.2f * u3;
        float pA = u0 * a4.x + u1 * a4.y + u2 * a4.z + u3 * a4.w;
        pA += __shfl_xor_sync(mask8, pA, 1);
        pA += __shfl_xor_sync(mask8, pA, 2);
        pA += __shfl_xor_sync(mask8, pA, 4);
        float eA = __expf(pA);
        dn += eA;
        acc0 += eA * xA.x; acc1 += eA * xA.y;
        acc2 += eA * xA.z; acc3 += eA * xA.w;
        i += 2;
    }
    if (i < cnt && sub == 0) {
        int sA = __ldg(&g_csrsrc[beg + i]);
        float4 xA = __ldg((const float4*)(g_xl + (size_t)sA * 64 + g * 4));
        float u0 = xA.x + xr4.x, u1 = xA.y + xr4.y, u2 = xA.z + xr4.z, u3 = xA.w + xr4.w;
        u0 = u0 > 0.f ? u0 : 0.2f * u0;  u1 = u1 > 0.f ? u1 : 0.2f * u1;
        u2 = u2 > 0.f ? u2 : 0.2f * u2;  u3 = u3 > 0.f ? u3 : 0.2f * u3;
        float pA = u0 * a4.x + u1 * a4.y + u2 * a4.z + u3 * a4.w;
        pA += __shfl_xor_sync(mask8, pA, 1);
        pA += __shfl_xor_sync(mask8, pA, 2);
        pA += __shfl_xor_sync(mask8, pA, 4);
        float eA = __expf(pA);
        dn += eA;
        acc0 += eA * xA.x; acc1 += eA * xA.y;
        acc2 += eA * xA.z; acc3 += eA * xA.w;
    }

    acc0 += __shfl_xor_sync(0xffffffffu, acc0, 16);
    acc1 += __shfl_xor_sync(0xffffffffu, acc1, 16);
    acc2 += __shfl_xor_sync(0xffffffffu, acc2, 16);
    acc3 += __shfl_xor_sync(0xffffffffu, acc3, 16);
    dn   += __shfl_xor_sync(0xffffffffu, dn, 16);

    if (sub == 0) {
        float r = 1.f / dn;
        int c = g * 4;
        float4 v;
        v.x = acc0 * r; v.y = acc1 * r; v.z = acc2 * r; v.w = acc3 * r;
        if (LAYER == 0) {
            v.x += bias[c + 0]; v.y += bias[c + 1];
            v.z += bias[c + 2]; v.w += bias[c + 3];
            v.x = v.x > 0.f ? v.x : 0.f;
            v.y = v.y > 0.f ? v.y : 0.f;
            v.z = v.z > 0.f ? v.z : 0.f;
            v.w = v.w > 0.f ? v.w : 0.f;
            *(float4*)(g_h + (size_t)n * 64 + c) = v;
        } else {
            *(float4*)(g_agg + (size_t)n * 64 + c) = v;
        }
    }
}

// ---------------------------------------------------------------------------
// Final head: b2 + BN + relu -> emb (Wp,bp) -> risk. Thread per node.
__global__ void k_final(const float* __restrict__ b2,
                        const float* __restrict__ bn_g, const float* __restrict__ bn_b,
                        const float* __restrict__ bn_m, const float* __restrict__ bn_v,
                        const float* __restrict__ Wp, const float* __restrict__ bp,
                        const float* __restrict__ Wh1, const float* __restrict__ bh1,
                        const float* __restrict__ Wh2, const float* __restrict__ bh2,
                        float* __restrict__ out) {
    int n = blockIdx.x * blockDim.x + threadIdx.x;
    if (n >= NN) return;

    float h[64];
    #pragma unroll
    for (int i = 0; i < 64; i++) {
        float v = g_agg[(size_t)n * 64 + i] + b2[i];
        v = (v - bn_m[i]) * rsqrtf(bn_v[i] + 1e-5f) * bn_g[i] + bn_b[i];
        h[i] = v > 0.f ? v : 0.f;
    }
    float emb[16];
    #pragma unroll
    for (int j = 0; j < 16; j++) emb[j] = bp[j];
    #pragma unroll
    for (int k = 0; k < 64; k++) {
        float hk = h[k];
        #pragma unroll
        for (int j = 0; j < 16; j++) emb[j] += hk * Wp[k * 16 + j];
    }
    #pragma unroll
    for (int j = 0; j < 16; j++) out[(size_t)n * 16 + j] = emb[j];

    float hid[8];
    #pragma unroll
    for (int j = 0; j < 8; j++) {
        float s = bh1[j];
        #pragma unroll
        for (int k = 0; k < 16; k++) s += emb[k] * Wh1[k * 8 + j];
        hid[j] = s > 0.f ? s : 0.f;
    }
    float risk = bh2[0];
    #pragma unroll
    for (int j = 0; j < 8; j++) risk += hid[j] * Wh2[j];
    out[(size_t)NN * 16 + n] = risk;
}

// ---------------------------------------------------------------------------
extern "C" void kernel_launch(void* const* d_in, const int* in_sizes, int n_in,
                              void* d_out, int out_size) {
    const float* x    = (const float*)d_in[0];
    const int*   ei   = (const int*)d_in[1];
    const float* Wl1  = (const float*)d_in[2];
    const float* bl1  = (const float*)d_in[3];
    const float* Wr1  = (const float*)d_in[4];
    const float* br1  = (const float*)d_in[5];
    const float* att1 = (const float*)d_in[6];
    const float* b1   = (const float*)d_in[7];
    const float* Wl2  = (const float*)d_in[8];
    const float* bl2  = (const float*)d_in[9];
    const float* Wr2  = (const float*)d_in[10];
    const float* br2  = (const float*)d_in[11];
    const float* att2 = (const float*)d_in[12];
    const float* b2   = (const float*)d_in[13];
    const float* bn_g = (const float*)d_in[14];
    const float* bn_b = (const float*)d_in[15];
    const float* bn_m = (const float*)d_in[16];
    const float* bn_v = (const float*)d_in[17];
    const float* Wp   = (const float*)d_in[18];
    const float* bp   = (const float*)d_in[19];
    const float* Wh1  = (const float*)d_in[20];
    const float* bh1  = (const float*)d_in[21];
    const float* Wh2  = (const float*)d_in[22];
    const float* bh2  = (const float*)d_in[23];
    float* out = (float*)d_out;

    float *p_xl, *p_xr, *p_h;
    cudaGetSymbolAddress((void**)&p_xl, g_xl);
    cudaGetSymbolAddress((void**)&p_xr, g_xr);
    cudaGetSymbolAddress((void**)&p_h,  g_h);

    const int RB = (NN + 255) / 256;
    const int CB = (ET + 255) / 256;
    const int GB = (NN + 63) / 64;
    const int WB = (NN * 32 + 255) / 256;

    k_reset<<<RB, 256>>>(ei);
    k_count<<<CB, 256>>>(ei);
    k_alloc<<<RB, 256>>>();
    k_scatter<<<CB, 256>>>(ei);
    k_gemm_fused<F_IN><<<GB, 256>>>(x, Wl1, bl1, Wr1, br1, p_xl, p_xr);
    k_edge_csr<0><<<WB, 256>>>(att1, b1);
    k_gemm_fused<HC><<<GB, 256>>>(p_h, Wl2, bl2, Wr2, br2, p_xl, p_xr);
    k_edge_csr<1><<<WB, 256>>>(att2, nullptr);
    k_final<<<(NN + 127) / 128, 128>>>(b2, bn_g, bn_b, bn_m, bn_v,
                                       Wp, bp, Wh1, bh1, Wh2, bh2, out);
}